// round 14
// baseline (speedup 1.0000x reference)
#include <cuda_runtime.h>
#include <cuda_fp16.h>
#include <cstdint>

// ----------------------------------------------------------------------------
// Problem dims (fixed by the dataset)
// ----------------------------------------------------------------------------
static constexpr int DN   = 8192;    // rows of x
static constexpr int DIN  = 4096;    // K
static constexpr int DOUT = 16384;   // output features

static constexpr int KBLK     = 64;            // K elems per k-block (128 B fp16 rows)
static constexpr int NUM_KBLK = DIN / KBLK;    // 64
static constexpr int M_TILE   = 128;
static constexpr int N_TILE   = 128;
static constexpr int STAGES   = 3;

// ----------------------------------------------------------------------------
// Device scratch: k-blocked, chunk-swizzled fp16 images of x and q.
// Element (row, k): kblk = k/64, col = k%64; 16B chunk c = col/8 stored at
// c ^ (row & 7). A CTA tile of one k-block is a CONTIGUOUS gmem span;
// smem is a verbatim copy, conflict-free for ldmatrix.
// ----------------------------------------------------------------------------
static constexpr size_t A_KBLK_BYTES = (size_t)DN   * 128;   // 1 MiB
static constexpr size_t B_KBLK_BYTES = (size_t)DOUT * 128;   // 2 MiB

__device__ __align__(128) unsigned char g_A[(size_t)NUM_KBLK * A_KBLK_BYTES]; //  64 MiB
__device__ __align__(128) unsigned char g_B[(size_t)NUM_KBLK * B_KBLK_BYTES]; // 128 MiB
__device__ float g_partial[2048];
__device__ float g_scale;

// ----------------------------------------------------------------------------
// PTX helpers (sm_90-baseline only; NO arch-'a' features)
// ----------------------------------------------------------------------------
__device__ __forceinline__ uint32_t s2u(const void* p) {
    uint32_t a;
    asm("{ .reg .u64 t; cvta.to.shared.u64 t, %1; cvt.u32.u64 %0, t; }" : "=r"(a) : "l"(p));
    return a;
}
#define CP_ASYNC16(s, g) \
    asm volatile("cp.async.cg.shared.global [%0], [%1], 16;" :: "r"(s), "l"(g))
#define CP_COMMIT() asm volatile("cp.async.commit_group;" ::: "memory")
#define CP_WAIT(n)  asm volatile("cp.async.wait_group %0;" :: "n"(n) : "memory")

#define LDSM_X4(r0, r1, r2, r3, a) \
    asm volatile("ldmatrix.sync.aligned.m8n8.x4.shared.b16 {%0,%1,%2,%3}, [%4];" \
                 : "=r"(r0), "=r"(r1), "=r"(r2), "=r"(r3) : "r"(a))

__device__ __forceinline__ void mma16816(float* d, const uint32_t* a, const uint32_t* b) {
    asm volatile(
        "mma.sync.aligned.m16n8k16.row.col.f32.f16.f16.f32 "
        "{%0,%1,%2,%3}, {%4,%5,%6,%7}, {%8,%9}, {%0,%1,%2,%3};"
        : "+f"(d[0]), "+f"(d[1]), "+f"(d[2]), "+f"(d[3])
        : "r"(a[0]), "r"(a[1]), "r"(a[2]), "r"(a[3]), "r"(b[0]), "r"(b[1]));
}

// ----------------------------------------------------------------------------
// Prep kernels (deterministic, no atomics)
// ----------------------------------------------------------------------------
__global__ void __launch_bounds__(256) k_maxabs(const float4* __restrict__ w, int n4) {
    __shared__ float red[8];
    float m = 0.f;
    for (int i = blockIdx.x * blockDim.x + threadIdx.x; i < n4; i += gridDim.x * blockDim.x) {
        float4 v = w[i];
        m = fmaxf(m, fmaxf(fmaxf(fabsf(v.x), fabsf(v.y)), fmaxf(fabsf(v.z), fabsf(v.w))));
    }
    #pragma unroll
    for (int o = 16; o > 0; o >>= 1) m = fmaxf(m, __shfl_xor_sync(0xFFFFFFFFu, m, o));
    if ((threadIdx.x & 31) == 0) red[threadIdx.x >> 5] = m;
    __syncthreads();
    if (threadIdx.x == 0) {
        float bm = red[0];
        #pragma unroll
        for (int i = 1; i < 8; i++) bm = fmaxf(bm, red[i]);
        g_partial[blockIdx.x] = bm;
    }
}

__device__ __forceinline__ float load_scale_from_partials(float* sred) {
    float m = 0.f;
    for (int i = threadIdx.x; i < 2048; i += 256) m = fmaxf(m, g_partial[i]);
    #pragma unroll
    for (int o = 16; o > 0; o >>= 1) m = fmaxf(m, __shfl_xor_sync(0xFFFFFFFFu, m, o));
    if ((threadIdx.x & 31) == 0) sred[threadIdx.x >> 5] = m;
    __syncthreads();
    float bm = sred[0];
    #pragma unroll
    for (int i = 1; i < 8; i++) bm = fmaxf(bm, sred[i]);
    return fmaxf(__fdiv_rn(bm, 7.0f), 1e-8f);
}

// Quantize weight exactly like the reference (fp32 div, rint = round-half-even,
// clip), store q as fp16 (exact small ints). One 16B chunk per thread per step.
__global__ void __launch_bounds__(256) k_quant(const float* __restrict__ w) {
    __shared__ float sred[8];
    const float scale = load_scale_from_partials(sred);
    if (blockIdx.x == 0 && threadIdx.x == 0) g_scale = scale;

    const int totalc = DOUT * (DIN / 8);          // 16B chunks
    for (int c = blockIdx.x * 256 + threadIdx.x; c < totalc; c += gridDim.x * 256) {
        int o    = c >> 9;            // DIN/8 = 512 chunks per row
        int r    = c & 511;
        int kblk = r >> 3;
        int ch   = r & 7;
        const float4* src = reinterpret_cast<const float4*>(w + (size_t)o * DIN + kblk * 64 + ch * 8);
        float4 v0 = src[0], v1 = src[1];
        __half2 h0 = __floats2half2_rn(fminf(fmaxf(rintf(__fdiv_rn(v0.x, scale)), -8.f), 7.f),
                                       fminf(fmaxf(rintf(__fdiv_rn(v0.y, scale)), -8.f), 7.f));
        __half2 h1 = __floats2half2_rn(fminf(fmaxf(rintf(__fdiv_rn(v0.z, scale)), -8.f), 7.f),
                                       fminf(fmaxf(rintf(__fdiv_rn(v0.w, scale)), -8.f), 7.f));
        __half2 h2 = __floats2half2_rn(fminf(fmaxf(rintf(__fdiv_rn(v1.x, scale)), -8.f), 7.f),
                                       fminf(fmaxf(rintf(__fdiv_rn(v1.y, scale)), -8.f), 7.f));
        __half2 h3 = __floats2half2_rn(fminf(fmaxf(rintf(__fdiv_rn(v1.z, scale)), -8.f), 7.f),
                                       fminf(fmaxf(rintf(__fdiv_rn(v1.w, scale)), -8.f), 7.f));
        uint4 pk;
        pk.x = *reinterpret_cast<uint32_t*>(&h0);
        pk.y = *reinterpret_cast<uint32_t*>(&h1);
        pk.z = *reinterpret_cast<uint32_t*>(&h2);
        pk.w = *reinterpret_cast<uint32_t*>(&h3);
        *reinterpret_cast<uint4*>(g_B + (size_t)kblk * B_KBLK_BYTES +
                                  (size_t)o * 128 + ((uint32_t)(ch ^ (o & 7)) << 4)) = pk;
    }
}

// Convert x to fp16 into the swizzled image. Same chunk scheme.
__global__ void __launch_bounds__(256) k_xcvt(const float* __restrict__ x) {
    const int totalc = DN * (DIN / 8);
    for (int c = blockIdx.x * 256 + threadIdx.x; c < totalc; c += gridDim.x * 256) {
        int row  = c >> 9;
        int r    = c & 511;
        int kblk = r >> 3;
        int ch   = r & 7;
        const float4* src = reinterpret_cast<const float4*>(x + (size_t)row * DIN + kblk * 64 + ch * 8);
        float4 v0 = src[0], v1 = src[1];
        __half2 h0 = __floats2half2_rn(v0.x, v0.y);
        __half2 h1 = __floats2half2_rn(v0.z, v0.w);
        __half2 h2 = __floats2half2_rn(v1.x, v1.y);
        __half2 h3 = __floats2half2_rn(v1.z, v1.w);
        uint4 pk;
        pk.x = *reinterpret_cast<uint32_t*>(&h0);
        pk.y = *reinterpret_cast<uint32_t*>(&h1);
        pk.z = *reinterpret_cast<uint32_t*>(&h2);
        pk.w = *reinterpret_cast<uint32_t*>(&h3);
        *reinterpret_cast<uint4*>(g_A + (size_t)kblk * A_KBLK_BYTES +
                                  (size_t)row * 128 + ((uint32_t)(ch ^ (row & 7)) << 4)) = pk;
    }
}

// ----------------------------------------------------------------------------
// GEMM: out[n,o] = scale * sum_k x_h[n,k] * q[o,k] + bias[o]
// CTA 128x128, 4 warps (2x2), warp tile 64x64, m16n8k16 HMMA,
// 3-stage cp.async pipeline, register double-buffered frags.
// 2 CTAs/SM co-residency hides barriers + epilogue.
// ----------------------------------------------------------------------------
static constexpr int A_STAGE = M_TILE * 128;            // 16 KiB
static constexpr int B_STAGE = N_TILE * 128;            // 16 KiB
static constexpr int STAGE_BYTES = A_STAGE + B_STAGE;   // 32 KiB
static constexpr int SMEM_DYN = STAGES * STAGE_BYTES;   // 96 KiB
static_assert(2 * SMEM_DYN <= 227 * 1024, "need 2 CTAs/SM");

__global__ void __launch_bounds__(128, 2) k_gemm(const float* __restrict__ bias,
                                                 float* __restrict__ out) {
    extern __shared__ char smem_raw[];
    const uint32_t sb = s2u(smem_raw);

    const int tid  = threadIdx.x;
    const int lane = tid & 31;
    const int wid  = tid >> 5;
    const int wr   = wid >> 1;          // 0..1 : m offset 64*wr
    const int wc   = wid & 1;           // 0..1 : n offset 64*wc

    // GROUP_M=8 rasterization over (64 m-tiles) x (128 n-tiles)
    const int bid    = blockIdx.x;
    const int grp    = bid >> 10;                 // / (8*128)
    const int wi     = bid & 1023;
    const int m_tile = (grp << 3) | (wi & 7);
    const int n_tile = wi >> 3;

    const unsigned char* gA = g_A + (size_t)m_tile * (M_TILE * 128);
    const unsigned char* gB = g_B + (size_t)n_tile * (N_TILE * 128);

    // producer: 128 threads copy A (1024 chunks) + B (1024 chunks) per stage
    auto issue_load = [&](int k) {
        const int s = k % STAGES;
        const uint32_t sA = sb + s * STAGE_BYTES;
        const uint32_t sB = sA + A_STAGE;
        const unsigned char* ga = gA + (size_t)k * A_KBLK_BYTES;
        const unsigned char* gb = gB + (size_t)k * B_KBLK_BYTES;
        #pragma unroll
        for (int j = 0; j < 8; j++) {
            int e = (tid + j * 128) * 16;
            CP_ASYNC16(sA + e, ga + e);
        }
        #pragma unroll
        for (int j = 0; j < 8; j++) {
            int e = (tid + j * 128) * 16;
            CP_ASYNC16(sB + e, gb + e);
        }
        CP_COMMIT();
    };

    auto load_a = [&](uint32_t (&af)[4][4], uint32_t sA, int kk) {
        #pragma unroll
        for (int mi = 0; mi < 4; mi++) {
            int row = wr * 64 + mi * 16 + (lane & 15);
            uint32_t ck = (uint32_t)(kk * 2 + (lane >> 4)) ^ ((uint32_t)row & 7u);
            LDSM_X4(af[mi][0], af[mi][1], af[mi][2], af[mi][3], sA + row * 128 + ck * 16);
        }
    };
    auto load_b = [&](uint32_t (&bf)[8][2], uint32_t sB, int kk) {
        #pragma unroll
        for (int np = 0; np < 4; np++) {
            int g = lane >> 3;                 // matrix group 0..3
            int row = wc * 64 + np * 16 + (g >> 1) * 8 + (lane & 7);
            uint32_t ck = (uint32_t)(kk * 2 + (g & 1)) ^ ((uint32_t)row & 7u);
            LDSM_X4(bf[2 * np][0], bf[2 * np][1], bf[2 * np + 1][0], bf[2 * np + 1][1],
                    sB + row * 128 + ck * 16);
        }
    };

    float acc[4][8][4];
    #pragma unroll
    for (int mi = 0; mi < 4; mi++)
        #pragma unroll
        for (int ni = 0; ni < 8; ni++)
            #pragma unroll
            for (int r = 0; r < 4; r++) acc[mi][ni][r] = 0.f;

    #pragma unroll
    for (int s = 0; s < STAGES - 1; s++) issue_load(s);

    uint32_t af[2][4][4], bf[2][8][2];

    for (int k = 0; k < NUM_KBLK; k++) {
        CP_WAIT(STAGES - 2);
        __syncthreads();
        if (k + STAGES - 1 < NUM_KBLK) issue_load(k + STAGES - 1);

        const uint32_t sA = sb + (k % STAGES) * STAGE_BYTES;
        const uint32_t sB = sA + A_STAGE;

        load_a(af[0], sA, 0);
        load_b(bf[0], sB, 0);

        #pragma unroll
        for (int kk = 0; kk < 4; kk++) {
            const int cur = kk & 1, nxt = cur ^ 1;
            if (kk < 3) {                      // prefetch next k16 while cur MMAs run
                load_a(af[nxt], sA, kk + 1);
                load_b(bf[nxt], sB, kk + 1);
            }
            #pragma unroll
            for (int mi = 0; mi < 4; mi++)
                #pragma unroll
                for (int ni = 0; ni < 8; ni++)
                    mma16816(acc[mi][ni], af[cur][mi], bf[cur][ni]);
        }
    }

    // ---------------- epilogue: out = scale*acc + bias ----------------
    const float scale = g_scale;
    const int rbase = m_tile * M_TILE + wr * 64 + (lane >> 2);
    const int cbase = n_tile * N_TILE + wc * 64 + (lane & 3) * 2;

    #pragma unroll
    for (int ni = 0; ni < 8; ni++) {
        const int col = cbase + ni * 8;
        const float2 bv = *reinterpret_cast<const float2*>(bias + col);
        #pragma unroll
        for (int mi = 0; mi < 4; mi++) {
            const int r0 = rbase + mi * 16;
            float2 v0, v1;
            v0.x = fmaf(acc[mi][ni][0], scale, bv.x);
            v0.y = fmaf(acc[mi][ni][1], scale, bv.y);
            v1.x = fmaf(acc[mi][ni][2], scale, bv.x);
            v1.y = fmaf(acc[mi][ni][3], scale, bv.y);
            *reinterpret_cast<float2*>(out + (size_t)r0 * DOUT + col)       = v0;
            *reinterpret_cast<float2*>(out + (size_t)(r0 + 8) * DOUT + col) = v1;
        }
    }
}

// ----------------------------------------------------------------------------
// Launch
// ----------------------------------------------------------------------------
extern "C" void kernel_launch(void* const* d_in, const int* in_sizes, int n_in,
                              void* d_out, int out_size) {
    (void)in_sizes; (void)n_in; (void)out_size;
    const float* x    = (const float*)d_in[0];
    const float* w    = (const float*)d_in[1];
    const float* bias = (const float*)d_in[2];
    float* out        = (float*)d_out;

    k_maxabs<<<2048, 256>>>((const float4*)w, DOUT * DIN / 4);
    k_xcvt<<<4096, 256>>>(x);
    k_quant<<<8192, 256>>>(w);

    cudaFuncSetAttribute(k_gemm, cudaFuncAttributeMaxDynamicSharedMemorySize, SMEM_DYN);
    k_gemm<<<(DN / M_TILE) * (DOUT / N_TILE), 128, SMEM_DYN>>>(bias, out);
}

// round 15
// speedup vs baseline: 1.0848x; 1.0848x over previous
#include <cuda_runtime.h>
#include <cuda_fp16.h>
#include <cstdint>

// ----------------------------------------------------------------------------
// Problem dims (fixed by the dataset)
// ----------------------------------------------------------------------------
static constexpr int DN   = 8192;    // rows of x
static constexpr int DIN  = 4096;    // K
static constexpr int DOUT = 16384;   // output features

static constexpr int KBLK     = 64;            // K elems per k-block (128 B fp16 rows)
static constexpr int NUM_KBLK = DIN / KBLK;    // 64
static constexpr int M_TILE   = 128;
static constexpr int N_TILE   = 256;
static constexpr int STAGES   = 4;

// ----------------------------------------------------------------------------
// Device scratch: k-blocked, chunk-swizzled fp16 images of x and q.
// Element (row, k): kblk = k/64, col = k%64; 16B chunk c = col/8 stored at
// c ^ (row & 7). A CTA tile of one k-block is a CONTIGUOUS gmem span;
// smem is a verbatim copy, conflict-free for ldmatrix.
// ----------------------------------------------------------------------------
static constexpr size_t A_KBLK_BYTES = (size_t)DN   * 128;   // 1 MiB
static constexpr size_t B_KBLK_BYTES = (size_t)DOUT * 128;   // 2 MiB

__device__ __align__(128) unsigned char g_A[(size_t)NUM_KBLK * A_KBLK_BYTES]; //  64 MiB
__device__ __align__(128) unsigned char g_B[(size_t)NUM_KBLK * B_KBLK_BYTES]; // 128 MiB
__device__ float g_partial[2048];
__device__ float g_scale;

// ----------------------------------------------------------------------------
// PTX helpers (sm_90-baseline only; NO arch-'a' features)
// ----------------------------------------------------------------------------
__device__ __forceinline__ uint32_t s2u(const void* p) {
    uint32_t a;
    asm("{ .reg .u64 t; cvta.to.shared.u64 t, %1; cvt.u32.u64 %0, t; }" : "=r"(a) : "l"(p));
    return a;
}
#define CP_ASYNC16(s, g) \
    asm volatile("cp.async.cg.shared.global [%0], [%1], 16;" :: "r"(s), "l"(g))
#define CP_COMMIT() asm volatile("cp.async.commit_group;" ::: "memory")
#define CP_WAIT(n)  asm volatile("cp.async.wait_group %0;" :: "n"(n) : "memory")

#define LDSM_X4(r0, r1, r2, r3, a) \
    asm volatile("ldmatrix.sync.aligned.m8n8.x4.shared.b16 {%0,%1,%2,%3}, [%4];" \
                 : "=r"(r0), "=r"(r1), "=r"(r2), "=r"(r3) : "r"(a))

__device__ __forceinline__ void mma16816(float* d, const uint32_t* a, const uint32_t* b) {
    asm volatile(
        "mma.sync.aligned.m16n8k16.row.col.f32.f16.f16.f32 "
        "{%0,%1,%2,%3}, {%4,%5,%6,%7}, {%8,%9}, {%0,%1,%2,%3};"
        : "+f"(d[0]), "+f"(d[1]), "+f"(d[2]), "+f"(d[3])
        : "r"(a[0]), "r"(a[1]), "r"(a[2]), "r"(a[3]), "r"(b[0]), "r"(b[1]));
}

// ----------------------------------------------------------------------------
// Prep kernels (deterministic, no atomics)
// ----------------------------------------------------------------------------
__global__ void __launch_bounds__(256) k_maxabs(const float4* __restrict__ w, int n4) {
    __shared__ float red[8];
    float m = 0.f;
    for (int i = blockIdx.x * blockDim.x + threadIdx.x; i < n4; i += gridDim.x * blockDim.x) {
        float4 v = w[i];
        m = fmaxf(m, fmaxf(fmaxf(fabsf(v.x), fabsf(v.y)), fmaxf(fabsf(v.z), fabsf(v.w))));
    }
    #pragma unroll
    for (int o = 16; o > 0; o >>= 1) m = fmaxf(m, __shfl_xor_sync(0xFFFFFFFFu, m, o));
    if ((threadIdx.x & 31) == 0) red[threadIdx.x >> 5] = m;
    __syncthreads();
    if (threadIdx.x == 0) {
        float bm = red[0];
        #pragma unroll
        for (int i = 1; i < 8; i++) bm = fmaxf(bm, red[i]);
        g_partial[blockIdx.x] = bm;
    }
}

__device__ __forceinline__ float load_scale_from_partials(float* sred) {
    float m = 0.f;
    for (int i = threadIdx.x; i < 2048; i += 256) m = fmaxf(m, g_partial[i]);
    #pragma unroll
    for (int o = 16; o > 0; o >>= 1) m = fmaxf(m, __shfl_xor_sync(0xFFFFFFFFu, m, o));
    if ((threadIdx.x & 31) == 0) sred[threadIdx.x >> 5] = m;
    __syncthreads();
    float bm = sred[0];
    #pragma unroll
    for (int i = 1; i < 8; i++) bm = fmaxf(bm, sred[i]);
    return fmaxf(__fdiv_rn(bm, 7.0f), 1e-8f);
}

// Quantize weight exactly like the reference (fp32 div, rint = round-half-even,
// clip), store q as fp16 (exact small ints). One 16B chunk per thread per step.
__global__ void __launch_bounds__(256) k_quant(const float* __restrict__ w) {
    __shared__ float sred[8];
    const float scale = load_scale_from_partials(sred);
    if (blockIdx.x == 0 && threadIdx.x == 0) g_scale = scale;

    const int totalc = DOUT * (DIN / 8);          // 16B chunks
    for (int c = blockIdx.x * 256 + threadIdx.x; c < totalc; c += gridDim.x * 256) {
        int o    = c >> 9;            // DIN/8 = 512 chunks per row
        int r    = c & 511;
        int kblk = r >> 3;
        int ch   = r & 7;
        const float4* src = reinterpret_cast<const float4*>(w + (size_t)o * DIN + kblk * 64 + ch * 8);
        float4 v0 = src[0], v1 = src[1];
        __half2 h0 = __floats2half2_rn(fminf(fmaxf(rintf(__fdiv_rn(v0.x, scale)), -8.f), 7.f),
                                       fminf(fmaxf(rintf(__fdiv_rn(v0.y, scale)), -8.f), 7.f));
        __half2 h1 = __floats2half2_rn(fminf(fmaxf(rintf(__fdiv_rn(v0.z, scale)), -8.f), 7.f),
                                       fminf(fmaxf(rintf(__fdiv_rn(v0.w, scale)), -8.f), 7.f));
        __half2 h2 = __floats2half2_rn(fminf(fmaxf(rintf(__fdiv_rn(v1.x, scale)), -8.f), 7.f),
                                       fminf(fmaxf(rintf(__fdiv_rn(v1.y, scale)), -8.f), 7.f));
        __half2 h3 = __floats2half2_rn(fminf(fmaxf(rintf(__fdiv_rn(v1.z, scale)), -8.f), 7.f),
                                       fminf(fmaxf(rintf(__fdiv_rn(v1.w, scale)), -8.f), 7.f));
        uint4 pk;
        pk.x = *reinterpret_cast<uint32_t*>(&h0);
        pk.y = *reinterpret_cast<uint32_t*>(&h1);
        pk.z = *reinterpret_cast<uint32_t*>(&h2);
        pk.w = *reinterpret_cast<uint32_t*>(&h3);
        *reinterpret_cast<uint4*>(g_B + (size_t)kblk * B_KBLK_BYTES +
                                  (size_t)o * 128 + ((uint32_t)(ch ^ (o & 7)) << 4)) = pk;
    }
}

// Convert x to fp16 into the swizzled image. Same chunk scheme.
__global__ void __launch_bounds__(256) k_xcvt(const float* __restrict__ x) {
    const int totalc = DN * (DIN / 8);
    for (int c = blockIdx.x * 256 + threadIdx.x; c < totalc; c += gridDim.x * 256) {
        int row  = c >> 9;
        int r    = c & 511;
        int kblk = r >> 3;
        int ch   = r & 7;
        const float4* src = reinterpret_cast<const float4*>(x + (size_t)row * DIN + kblk * 64 + ch * 8);
        float4 v0 = src[0], v1 = src[1];
        __half2 h0 = __floats2half2_rn(v0.x, v0.y);
        __half2 h1 = __floats2half2_rn(v0.z, v0.w);
        __half2 h2 = __floats2half2_rn(v1.x, v1.y);
        __half2 h3 = __floats2half2_rn(v1.z, v1.w);
        uint4 pk;
        pk.x = *reinterpret_cast<uint32_t*>(&h0);
        pk.y = *reinterpret_cast<uint32_t*>(&h1);
        pk.z = *reinterpret_cast<uint32_t*>(&h2);
        pk.w = *reinterpret_cast<uint32_t*>(&h3);
        *reinterpret_cast<uint4*>(g_A + (size_t)kblk * A_KBLK_BYTES +
                                  (size_t)row * 128 + ((uint32_t)(ch ^ (row & 7)) << 4)) = pk;
    }
}

// ----------------------------------------------------------------------------
// GEMM: out[n,o] = scale * sum_k x_h[n,k] * q[o,k] + bias[o]
// CTA 128x256, 8 warps (2x4), warp tile 64x64, m16n8k16 HMMA, 4-stage
// cp.async pipeline. Producer issues spread across the kk loop; fragments
// double-buffered in registers with cross-kblk prefetch (no boundary bubble).
// ----------------------------------------------------------------------------
static constexpr int A_STAGE = M_TILE * 128;            // 16 KiB
static constexpr int B_STAGE = N_TILE * 128;            // 32 KiB
static constexpr int STAGE_BYTES = A_STAGE + B_STAGE;   // 48 KiB
static constexpr int SMEM_DYN = STAGES * STAGE_BYTES;   // 192 KiB
static_assert(SMEM_DYN <= 227 * 1024, "smem over limit");

__global__ void __launch_bounds__(256, 1) k_gemm(const float* __restrict__ bias,
                                                 float* __restrict__ out) {
    extern __shared__ char smem_raw[];
    const uint32_t sb = s2u(smem_raw);

    const int tid  = threadIdx.x;
    const int lane = tid & 31;
    const int wid  = tid >> 5;
    const int wr   = wid >> 2;          // 0..1 : m offset 64*wr
    const int wc   = wid & 3;           // 0..3 : n offset 64*wc

    // GROUP_M=8 rasterization over (64 m-tiles) x (64 n-tiles)
    const int bid    = blockIdx.x;
    const int grp    = bid >> 9;                  // / (8*64)
    const int wi     = bid & 511;
    const int m_tile = (grp << 3) | (wi & 7);
    const int n_tile = wi >> 3;

    const unsigned char* gA = g_A + (size_t)m_tile * (M_TILE * 128);
    const unsigned char* gB = g_B + (size_t)n_tile * (N_TILE * 128);

    // full-stage producer (prologue only)
    auto issue_load = [&](int k) {
        const int s = k % STAGES;
        const uint32_t sA = sb + s * STAGE_BYTES;
        const uint32_t sB = sA + A_STAGE;
        const unsigned char* ga = gA + (size_t)k * A_KBLK_BYTES;
        const unsigned char* gb = gB + (size_t)k * B_KBLK_BYTES;
        #pragma unroll
        for (int j = 0; j < 4; j++) {
            int e = (tid + j * 256) * 16;
            CP_ASYNC16(sA + e, ga + e);
        }
        #pragma unroll
        for (int j = 0; j < 8; j++) {
            int e = (tid + j * 256) * 16;
            CP_ASYNC16(sB + e, gb + e);
        }
        CP_COMMIT();
    };

    auto load_a = [&](uint32_t (&af)[4][4], uint32_t sA, int kk) {
        #pragma unroll
        for (int mi = 0; mi < 4; mi++) {
            int row = wr * 64 + mi * 16 + (lane & 15);
            uint32_t ck = (uint32_t)(kk * 2 + (lane >> 4)) ^ ((uint32_t)row & 7u);
            LDSM_X4(af[mi][0], af[mi][1], af[mi][2], af[mi][3], sA + row * 128 + ck * 16);
        }
    };
    auto load_b = [&](uint32_t (&bf)[8][2], uint32_t sB, int kk) {
        #pragma unroll
        for (int np = 0; np < 4; np++) {
            int g = lane >> 3;                 // matrix group 0..3
            int row = wc * 64 + np * 16 + (g >> 1) * 8 + (lane & 7);
            uint32_t ck = (uint32_t)(kk * 2 + (g & 1)) ^ ((uint32_t)row & 7u);
            LDSM_X4(bf[2 * np][0], bf[2 * np][1], bf[2 * np + 1][0], bf[2 * np + 1][1],
                    sB + row * 128 + ck * 16);
        }
    };

    float acc[4][8][4];
    #pragma unroll
    for (int mi = 0; mi < 4; mi++)
        #pragma unroll
        for (int ni = 0; ni < 8; ni++)
            #pragma unroll
            for (int r = 0; r < 4; r++) acc[mi][ni][r] = 0.f;

    #pragma unroll
    for (int s = 0; s < STAGES - 1; s++) issue_load(s);

    uint32_t af[2][4][4], bf[2][8][2];

    // stage 0 complete (3 committed, wait<=2), publish, preload first frags
    CP_WAIT(2);
    __syncthreads();
    load_a(af[0], sb, 0);
    load_b(bf[0], sb + A_STAGE, 0);

    for (int k = 0; k < NUM_KBLK; k++) {
        // wait<=1: stages k AND k+1 complete -> cross-kblk prefetch is safe
        CP_WAIT(1);
        __syncthreads();

        const uint32_t sA = sb + (k % STAGES) * STAGE_BYTES;
        const uint32_t sB = sA + A_STAGE;

        const int kn = k + STAGES - 1;            // stage to fill this iter
        const bool do_issue = (kn < NUM_KBLK);
        const uint32_t nsA = sb + (kn % STAGES) * STAGE_BYTES;
        const uint32_t nsB = nsA + A_STAGE;
        const unsigned char* nga = gA + (size_t)kn * A_KBLK_BYTES;
        const unsigned char* ngb = gB + (size_t)kn * B_KBLK_BYTES;

        #pragma unroll
        for (int kk = 0; kk < 4; kk++) {
            const int cur = kk & 1, nxt = cur ^ 1;

            // spread producer: 3 of 12 chunks per kk  (j<4: A, else B)
            if (do_issue) {
                #pragma unroll
                for (int jj = 0; jj < 3; jj++) {
                    const int j = kk * 3 + jj;
                    if (j < 4) {
                        int e = (tid + j * 256) * 16;
                        CP_ASYNC16(nsA + e, nga + e);
                    } else {
                        int e = (tid + (j - 4) * 256) * 16;
                        CP_ASYNC16(nsB + e, ngb + e);
                    }
                }
            }

            // fragment prefetch: next kk, or kk=0 of NEXT k-block (stage k+1)
            if (kk < 3) {
                load_a(af[nxt], sA, kk + 1);
                load_b(bf[nxt], sB, kk + 1);
            } else if (k + 1 < NUM_KBLK) {
                const uint32_t pA = sb + ((k + 1) % STAGES) * STAGE_BYTES;
                load_a(af[nxt], pA, 0);
                load_b(bf[nxt], pA + A_STAGE, 0);
            }

            #pragma unroll
            for (int mi = 0; mi < 4; mi++)
                #pragma unroll
                for (int ni = 0; ni < 8; ni++)
                    mma16816(acc[mi][ni], af[cur][mi], bf[cur][ni]);
        }
        if (do_issue) CP_COMMIT();
    }

    // ---------------- epilogue: out = scale*acc + bias ----------------
    const float scale = g_scale;
    const int rbase = m_tile * M_TILE + wr * 64 + (lane >> 2);
    const int cbase = n_tile * N_TILE + wc * 64 + (lane & 3) * 2;

    #pragma unroll
    for (int ni = 0; ni < 8; ni++) {
        const int col = cbase + ni * 8;
        const float2 bv = *reinterpret_cast<const float2*>(bias + col);
        #pragma unroll
        for (int mi = 0; mi < 4; mi++) {
            const int r0 = rbase + mi * 16;
            float2 v0, v1;
            v0.x = fmaf(acc[mi][ni][0], scale, bv.x);
            v0.y = fmaf(acc[mi][ni][1], scale, bv.y);
            v1.x = fmaf(acc[mi][ni][2], scale, bv.x);
            v1.y = fmaf(acc[mi][ni][3], scale, bv.y);
            *reinterpret_cast<float2*>(out + (size_t)r0 * DOUT + col)       = v0;
            *reinterpret_cast<float2*>(out + (size_t)(r0 + 8) * DOUT + col) = v1;
        }
    }
}

// ----------------------------------------------------------------------------
// Launch
// ----------------------------------------------------------------------------
extern "C" void kernel_launch(void* const* d_in, const int* in_sizes, int n_in,
                              void* d_out, int out_size) {
    (void)in_sizes; (void)n_in; (void)out_size;
    const float* x    = (const float*)d_in[0];
    const float* w    = (const float*)d_in[1];
    const float* bias = (const float*)d_in[2];
    float* out        = (float*)d_out;

    k_maxabs<<<2048, 256>>>((const float4*)w, DOUT * DIN / 4);
    k_xcvt<<<4096, 256>>>(x);
    k_quant<<<8192, 256>>>(w);

    cudaFuncSetAttribute(k_gemm, cudaFuncAttributeMaxDynamicSharedMemorySize, SMEM_DYN);
    k_gemm<<<(DN / M_TILE) * (DOUT / N_TILE), 256, SMEM_DYN>>>(bias, out);
}

// round 16
// speedup vs baseline: 1.5653x; 1.4429x over previous
#include <cuda_runtime.h>
#include <cuda_fp16.h>
#include <cstdint>

// ----------------------------------------------------------------------------
// Problem dims (fixed by the dataset)
// ----------------------------------------------------------------------------
static constexpr int DN   = 8192;    // rows of x
static constexpr int DIN  = 4096;    // K
static constexpr int DOUT = 16384;   // output features

static constexpr int KBLK     = 64;            // K elems per k-block (128 B fp16 rows)
static constexpr int NUM_KBLK = DIN / KBLK;    // 64
static constexpr int M_TILE   = 128;
static constexpr int N_TILE   = 256;
static constexpr int STAGES   = 4;

// ----------------------------------------------------------------------------
// Device scratch: k-blocked, chunk-swizzled fp16 images of x and q.
// Element (row, k): kblk = k/64, col = k%64; 16B chunk c = col/8 stored at
// c ^ (row & 7). A CTA tile of one k-block is a CONTIGUOUS gmem span;
// smem is a verbatim copy, conflict-free for ldmatrix.
// ----------------------------------------------------------------------------
static constexpr size_t A_KBLK_BYTES = (size_t)DN   * 128;   // 1 MiB
static constexpr size_t B_KBLK_BYTES = (size_t)DOUT * 128;   // 2 MiB

__device__ __align__(128) unsigned char g_A[(size_t)NUM_KBLK * A_KBLK_BYTES]; //  64 MiB
__device__ __align__(128) unsigned char g_B[(size_t)NUM_KBLK * B_KBLK_BYTES]; // 128 MiB
__device__ float g_partial[2048];
__device__ float g_scale;

// ----------------------------------------------------------------------------
// PTX helpers (sm_90-baseline only; NO arch-'a' features)
// ----------------------------------------------------------------------------
__device__ __forceinline__ uint32_t s2u(const void* p) {
    uint32_t a;
    asm("{ .reg .u64 t; cvta.to.shared.u64 t, %1; cvt.u32.u64 %0, t; }" : "=r"(a) : "l"(p));
    return a;
}
#define CP_ASYNC16(s, g) \
    asm volatile("cp.async.cg.shared.global [%0], [%1], 16;" :: "r"(s), "l"(g))
#define CP_COMMIT() asm volatile("cp.async.commit_group;" ::: "memory")
#define CP_WAIT(n)  asm volatile("cp.async.wait_group %0;" :: "n"(n) : "memory")

#define LDSM_X4(r0, r1, r2, r3, a) \
    asm volatile("ldmatrix.sync.aligned.m8n8.x4.shared.b16 {%0,%1,%2,%3}, [%4];" \
                 : "=r"(r0), "=r"(r1), "=r"(r2), "=r"(r3) : "r"(a))

__device__ __forceinline__ void mma16816(float* d, const uint32_t* a, const uint32_t* b) {
    asm volatile(
        "mma.sync.aligned.m16n8k16.row.col.f32.f16.f16.f32 "
        "{%0,%1,%2,%3}, {%4,%5,%6,%7}, {%8,%9}, {%0,%1,%2,%3};"
        : "+f"(d[0]), "+f"(d[1]), "+f"(d[2]), "+f"(d[3])
        : "r"(a[0]), "r"(a[1]), "r"(a[2]), "r"(a[3]), "r"(b[0]), "r"(b[1]));
}

// ----------------------------------------------------------------------------
// Prep kernels (deterministic, no atomics)
// ----------------------------------------------------------------------------
__global__ void __launch_bounds__(256) k_maxabs(const float4* __restrict__ w, int n4) {
    __shared__ float red[8];
    float m = 0.f;
    for (int i = blockIdx.x * blockDim.x + threadIdx.x; i < n4; i += gridDim.x * blockDim.x) {
        float4 v = w[i];
        m = fmaxf(m, fmaxf(fmaxf(fabsf(v.x), fabsf(v.y)), fmaxf(fabsf(v.z), fabsf(v.w))));
    }
    #pragma unroll
    for (int o = 16; o > 0; o >>= 1) m = fmaxf(m, __shfl_xor_sync(0xFFFFFFFFu, m, o));
    if ((threadIdx.x & 31) == 0) red[threadIdx.x >> 5] = m;
    __syncthreads();
    if (threadIdx.x == 0) {
        float bm = red[0];
        #pragma unroll
        for (int i = 1; i < 8; i++) bm = fmaxf(bm, red[i]);
        g_partial[blockIdx.x] = bm;
    }
}

__device__ __forceinline__ float load_scale_from_partials(float* sred) {
    float m = 0.f;
    for (int i = threadIdx.x; i < 2048; i += 256) m = fmaxf(m, g_partial[i]);
    #pragma unroll
    for (int o = 16; o > 0; o >>= 1) m = fmaxf(m, __shfl_xor_sync(0xFFFFFFFFu, m, o));
    if ((threadIdx.x & 31) == 0) sred[threadIdx.x >> 5] = m;
    __syncthreads();
    float bm = sred[0];
    #pragma unroll
    for (int i = 1; i < 8; i++) bm = fmaxf(bm, sred[i]);
    return fmaxf(__fdiv_rn(bm, 7.0f), 1e-8f);
}

// Quantize weight exactly like the reference (fp32 div, rint = round-half-even,
// clip), store q as fp16 (exact small ints). One 16B chunk per thread per step.
__global__ void __launch_bounds__(256) k_quant(const float* __restrict__ w) {
    __shared__ float sred[8];
    const float scale = load_scale_from_partials(sred);
    if (blockIdx.x == 0 && threadIdx.x == 0) g_scale = scale;

    const int totalc = DOUT * (DIN / 8);          // 16B chunks
    for (int c = blockIdx.x * 256 + threadIdx.x; c < totalc; c += gridDim.x * 256) {
        int o    = c >> 9;            // DIN/8 = 512 chunks per row
        int r    = c & 511;
        int kblk = r >> 3;
        int ch   = r & 7;
        const float4* src = reinterpret_cast<const float4*>(w + (size_t)o * DIN + kblk * 64 + ch * 8);
        float4 v0 = src[0], v1 = src[1];
        __half2 h0 = __floats2half2_rn(fminf(fmaxf(rintf(__fdiv_rn(v0.x, scale)), -8.f), 7.f),
                                       fminf(fmaxf(rintf(__fdiv_rn(v0.y, scale)), -8.f), 7.f));
        __half2 h1 = __floats2half2_rn(fminf(fmaxf(rintf(__fdiv_rn(v0.z, scale)), -8.f), 7.f),
                                       fminf(fmaxf(rintf(__fdiv_rn(v0.w, scale)), -8.f), 7.f));
        __half2 h2 = __floats2half2_rn(fminf(fmaxf(rintf(__fdiv_rn(v1.x, scale)), -8.f), 7.f),
                                       fminf(fmaxf(rintf(__fdiv_rn(v1.y, scale)), -8.f), 7.f));
        __half2 h3 = __floats2half2_rn(fminf(fmaxf(rintf(__fdiv_rn(v1.z, scale)), -8.f), 7.f),
                                       fminf(fmaxf(rintf(__fdiv_rn(v1.w, scale)), -8.f), 7.f));
        uint4 pk;
        pk.x = *reinterpret_cast<uint32_t*>(&h0);
        pk.y = *reinterpret_cast<uint32_t*>(&h1);
        pk.z = *reinterpret_cast<uint32_t*>(&h2);
        pk.w = *reinterpret_cast<uint32_t*>(&h3);
        *reinterpret_cast<uint4*>(g_B + (size_t)kblk * B_KBLK_BYTES +
                                  (size_t)o * 128 + ((uint32_t)(ch ^ (o & 7)) << 4)) = pk;
    }
}

// Convert x to fp16 into the swizzled image. Same chunk scheme.
__global__ void __launch_bounds__(256) k_xcvt(const float* __restrict__ x) {
    const int totalc = DN * (DIN / 8);
    for (int c = blockIdx.x * 256 + threadIdx.x; c < totalc; c += gridDim.x * 256) {
        int row  = c >> 9;
        int r    = c & 511;
        int kblk = r >> 3;
        int ch   = r & 7;
        const float4* src = reinterpret_cast<const float4*>(x + (size_t)row * DIN + kblk * 64 + ch * 8);
        float4 v0 = src[0], v1 = src[1];
        __half2 h0 = __floats2half2_rn(v0.x, v0.y);
        __half2 h1 = __floats2half2_rn(v0.z, v0.w);
        __half2 h2 = __floats2half2_rn(v1.x, v1.y);
        __half2 h3 = __floats2half2_rn(v1.z, v1.w);
        uint4 pk;
        pk.x = *reinterpret_cast<uint32_t*>(&h0);
        pk.y = *reinterpret_cast<uint32_t*>(&h1);
        pk.z = *reinterpret_cast<uint32_t*>(&h2);
        pk.w = *reinterpret_cast<uint32_t*>(&h3);
        *reinterpret_cast<uint4*>(g_A + (size_t)kblk * A_KBLK_BYTES +
                                  (size_t)row * 128 + ((uint32_t)(ch ^ (row & 7)) << 4)) = pk;
    }
}

// ----------------------------------------------------------------------------
// GEMM: out[n,o] = scale * sum_k x_h[n,k] * q[o,k] + bias[o]
// CTA 128x256, 8 warps (2x4), warp tile 64x64, m16n8k16 HMMA, 4-stage
// cp.async pipeline (burst producer at top of iter, OUTSIDE the MMA stream).
// Register double-buffered fragments WITH cross-kblk prefetch: at kk=3 the
// idle buffer is filled with kk=0 of stage k+1 (resident thanks to wait<=1),
// so MMAs never stall on a cold LDSM at the k-block boundary.
// ----------------------------------------------------------------------------
static constexpr int A_STAGE = M_TILE * 128;            // 16 KiB
static constexpr int B_STAGE = N_TILE * 128;            // 32 KiB
static constexpr int STAGE_BYTES = A_STAGE + B_STAGE;   // 48 KiB
static constexpr int SMEM_DYN = STAGES * STAGE_BYTES;   // 192 KiB
static_assert(SMEM_DYN <= 227 * 1024, "smem over limit");

__global__ void __launch_bounds__(256, 1) k_gemm(const float* __restrict__ bias,
                                                 float* __restrict__ out) {
    extern __shared__ char smem_raw[];
    const uint32_t sb = s2u(smem_raw);

    const int tid  = threadIdx.x;
    const int lane = tid & 31;
    const int wid  = tid >> 5;
    const int wr   = wid >> 2;          // 0..1 : m offset 64*wr
    const int wc   = wid & 3;           // 0..3 : n offset 64*wc

    // GROUP_M=8 rasterization over (64 m-tiles) x (64 n-tiles)
    const int bid    = blockIdx.x;
    const int grp    = bid >> 9;                  // / (8*64)
    const int wi     = bid & 511;
    const int m_tile = (grp << 3) | (wi & 7);
    const int n_tile = wi >> 3;

    const unsigned char* gA = g_A + (size_t)m_tile * (M_TILE * 128);
    const unsigned char* gB = g_B + (size_t)n_tile * (N_TILE * 128);

    // burst producer: 256 threads copy A (1024 chunks) + B (2048 chunks)
    auto issue_load = [&](int k) {
        const int s = k % STAGES;
        const uint32_t sA = sb + s * STAGE_BYTES;
        const uint32_t sB = sA + A_STAGE;
        const unsigned char* ga = gA + (size_t)k * A_KBLK_BYTES;
        const unsigned char* gb = gB + (size_t)k * B_KBLK_BYTES;
        #pragma unroll
        for (int j = 0; j < 4; j++) {
            int e = (tid + j * 256) * 16;
            CP_ASYNC16(sA + e, ga + e);
        }
        #pragma unroll
        for (int j = 0; j < 8; j++) {
            int e = (tid + j * 256) * 16;
            CP_ASYNC16(sB + e, gb + e);
        }
        CP_COMMIT();
    };

    auto load_a = [&](uint32_t (&af)[4][4], uint32_t sA, int kk) {
        #pragma unroll
        for (int mi = 0; mi < 4; mi++) {
            int row = wr * 64 + mi * 16 + (lane & 15);
            uint32_t ck = (uint32_t)(kk * 2 + (lane >> 4)) ^ ((uint32_t)row & 7u);
            LDSM_X4(af[mi][0], af[mi][1], af[mi][2], af[mi][3], sA + row * 128 + ck * 16);
        }
    };
    auto load_b = [&](uint32_t (&bf)[8][2], uint32_t sB, int kk) {
        #pragma unroll
        for (int np = 0; np < 4; np++) {
            int g = lane >> 3;                 // matrix group 0..3
            int row = wc * 64 + np * 16 + (g >> 1) * 8 + (lane & 7);
            uint32_t ck = (uint32_t)(kk * 2 + (g & 1)) ^ ((uint32_t)row & 7u);
            LDSM_X4(bf[2 * np][0], bf[2 * np][1], bf[2 * np + 1][0], bf[2 * np + 1][1],
                    sB + row * 128 + ck * 16);
        }
    };

    float acc[4][8][4];
    #pragma unroll
    for (int mi = 0; mi < 4; mi++)
        #pragma unroll
        for (int ni = 0; ni < 8; ni++)
            #pragma unroll
            for (int r = 0; r < 4; r++) acc[mi][ni][r] = 0.f;

    #pragma unroll
    for (int s = 0; s < STAGES - 1; s++) issue_load(s);

    uint32_t af[2][4][4], bf[2][8][2];

    // stage 0 complete (3 committed, wait<=2), publish, preload first frags
    CP_WAIT(2);
    __syncthreads();
    load_a(af[0], sb, 0);
    load_b(bf[0], sb + A_STAGE, 0);

    for (int k = 0; k < NUM_KBLK; k++) {
        // wait<=1: stages k AND k+1 complete -> cross-kblk prefetch is safe
        CP_WAIT(1);
        __syncthreads();
        if (k + STAGES - 1 < NUM_KBLK) issue_load(k + STAGES - 1);

        const uint32_t sA = sb + (k % STAGES) * STAGE_BYTES;
        const uint32_t sB = sA + A_STAGE;

        #pragma unroll
        for (int kk = 0; kk < 4; kk++) {
            const int cur = kk & 1, nxt = cur ^ 1;
            if (kk < 3) {                      // prefetch next k16 while cur MMAs run
                load_a(af[nxt], sA, kk + 1);
                load_b(bf[nxt], sB, kk + 1);
            } else if (k + 1 < NUM_KBLK) {     // prefetch kk=0 of NEXT k-block
                const uint32_t pA = sb + ((k + 1) % STAGES) * STAGE_BYTES;
                load_a(af[nxt], pA, 0);
                load_b(bf[nxt], pA + A_STAGE, 0);
            }
            #pragma unroll
            for (int mi = 0; mi < 4; mi++)
                #pragma unroll
                for (int ni = 0; ni < 8; ni++)
                    mma16816(acc[mi][ni], af[cur][mi], bf[cur][ni]);
        }
    }

    // ---------------- epilogue: out = scale*acc + bias ----------------
    const float scale = g_scale;
    const int rbase = m_tile * M_TILE + wr * 64 + (lane >> 2);
    const int cbase = n_tile * N_TILE + wc * 64 + (lane & 3) * 2;

    #pragma unroll
    for (int ni = 0; ni < 8; ni++) {
        const int col = cbase + ni * 8;
        const float2 bv = *reinterpret_cast<const float2*>(bias + col);
        #pragma unroll
        for (int mi = 0; mi < 4; mi++) {
            const int r0 = rbase + mi * 16;
            float2 v0, v1;
            v0.x = fmaf(acc[mi][ni][0], scale, bv.x);
            v0.y = fmaf(acc[mi][ni][1], scale, bv.y);
            v1.x = fmaf(acc[mi][ni][2], scale, bv.x);
            v1.y = fmaf(acc[mi][ni][3], scale, bv.y);
            *reinterpret_cast<float2*>(out + (size_t)r0 * DOUT + col)       = v0;
            *reinterpret_cast<float2*>(out + (size_t)(r0 + 8) * DOUT + col) = v1;
        }
    }
}

// ----------------------------------------------------------------------------
// Launch
// ----------------------------------------------------------------------------
extern "C" void kernel_launch(void* const* d_in, const int* in_sizes, int n_in,
                              void* d_out, int out_size) {
    (void)in_sizes; (void)n_in; (void)out_size;
    const float* x    = (const float*)d_in[0];
    const float* w    = (const float*)d_in[1];
    const float* bias = (const float*)d_in[2];
    float* out        = (float*)d_out;

    k_maxabs<<<2048, 256>>>((const float4*)w, DOUT * DIN / 4);
    k_xcvt<<<4096, 256>>>(x);
    k_quant<<<8192, 256>>>(w);

    cudaFuncSetAttribute(k_gemm, cudaFuncAttributeMaxDynamicSharedMemorySize, SMEM_DYN);
    k_gemm<<<(DN / M_TILE) * (DOUT / N_TILE), 256, SMEM_DYN>>>(bias, out);
}